// round 8
// baseline (speedup 1.0000x reference)
#include <cuda_runtime.h>
#include <cstdint>

// out[dst[e], :] += w[e] * x[src[e], :]
// Fixed-capacity dst-binning (no scan) + per-node register-accumulated gather
// writing each output row exactly once. Overflow (P~1e-36 for Poisson(10) with
// cap 64) handled by an atomic fallback kernel for correctness.

static constexpr int F = 64;
static constexpr int THREADS = 256;
static constexpr int BIN_THREADS = 512;
static constexpr int N_MAX = 1 << 17;       // 131072 >= 100000
static constexpr int E_MAX = 1 << 21;       // 2M >= 1M
static constexpr int MAX_DEG = 64;

// Scratch (static device globals: allocation-free).
__device__ int g_cursor[N_MAX + 1];                          // [N] = overflow count
__device__ unsigned long long g_sw[(size_t)N_MAX * MAX_DEG]; // packed (w<<32)|src per dst-bin
__device__ int g_ovf[E_MAX];                                 // overflowed edge ids

// ---------- 1. bin edges by dst: 8 edges/thread, atomics batched before stores ----------
__global__ void __launch_bounds__(BIN_THREADS)
k_binplace(const float* __restrict__ ew, const int* __restrict__ ei, int E, int N)
{
    int t = blockIdx.x * BIN_THREADS + threadIdx.x;
    int octs = E >> 3;
    if (t < octs) {
        int e0 = t * 8;
        int4   sa = __ldcs(reinterpret_cast<const int4*>(ei + e0));
        int4   sb = __ldcs(reinterpret_cast<const int4*>(ei + e0 + 4));
        int4   da = __ldcs(reinterpret_cast<const int4*>(ei + E + e0));
        int4   db = __ldcs(reinterpret_cast<const int4*>(ei + E + e0 + 4));
        float4 wa = __ldcs(reinterpret_cast<const float4*>(ew + e0));
        float4 wb = __ldcs(reinterpret_cast<const float4*>(ew + e0 + 4));

        int s[8] = {sa.x, sa.y, sa.z, sa.w, sb.x, sb.y, sb.z, sb.w};
        int d[8] = {da.x, da.y, da.z, da.w, db.x, db.y, db.z, db.w};
        float w[8] = {wa.x, wa.y, wa.z, wa.w, wb.x, wb.y, wb.z, wb.w};

        // Phase 1: 8 independent cursor atomics in flight (hide ATOMG latency).
        int c[8];
        #pragma unroll
        for (int k = 0; k < 8; k++) c[k] = atomicAdd(&g_cursor[d[k]], 1);

        // Phase 2: 8 independent bin stores.
        #pragma unroll
        for (int k = 0; k < 8; k++) {
            if (c[k] < MAX_DEG)
                g_sw[(size_t)d[k] * MAX_DEG + c[k]] =
                    ((unsigned long long)__float_as_uint(w[k]) << 32) | (unsigned int)s[k];
            else
                g_ovf[atomicAdd(&g_cursor[N], 1)] = e0 + k;
        }
    } else {
        // tail edges (E not multiple of 8)
        int e = octs * 8 + (t - octs);
        if (e < E) {
            int sv = __ldg(&ei[e]);
            int dv = __ldg(&ei[E + e]);
            float wv = __ldg(&ew[e]);
            int c = atomicAdd(&g_cursor[dv], 1);
            if (c < MAX_DEG)
                g_sw[(size_t)dv * MAX_DEG + c] =
                    ((unsigned long long)__float_as_uint(wv) << 32) | (unsigned int)sv;
            else
                g_ovf[atomicAdd(&g_cursor[N], 1)] = e;
        }
    }
}

// ---------- 2. per-node gather: one warp per node, float2 per lane ----------
__global__ void __launch_bounds__(THREADS)
k_gather(const float* __restrict__ x, float* __restrict__ out, int N)
{
    int warp = (blockIdx.x * THREADS + threadIdx.x) >> 5;
    int lane = threadIdx.x & 31;
    if (warp >= N) return;

    int deg = g_cursor[warp];
    if (deg > MAX_DEG) deg = MAX_DEG;
    const unsigned long long* sw = g_sw + (size_t)warp * MAX_DEG;

    float2 acc = make_float2(0.f, 0.f);
    int co = lane * 2;

    int j = 0;
    for (; j + 4 <= deg; j += 4) {
        ulonglong2 p0 = __ldcs(reinterpret_cast<const ulonglong2*>(sw + j));
        ulonglong2 p1 = __ldcs(reinterpret_cast<const ulonglong2*>(sw + j + 2));
        int   s0 = (int)(unsigned int)p0.x, s1 = (int)(unsigned int)p0.y;
        int   s2 = (int)(unsigned int)p1.x, s3 = (int)(unsigned int)p1.y;
        float w0 = __uint_as_float((unsigned int)(p0.x >> 32));
        float w1 = __uint_as_float((unsigned int)(p0.y >> 32));
        float w2 = __uint_as_float((unsigned int)(p1.x >> 32));
        float w3 = __uint_as_float((unsigned int)(p1.y >> 32));
        // 4 independent row loads (MLP=4), each fully coalesced 256B warp-wide.
        float2 v0 = __ldg(reinterpret_cast<const float2*>(x + (long long)s0 * F + co));
        float2 v1 = __ldg(reinterpret_cast<const float2*>(x + (long long)s1 * F + co));
        float2 v2 = __ldg(reinterpret_cast<const float2*>(x + (long long)s2 * F + co));
        float2 v3 = __ldg(reinterpret_cast<const float2*>(x + (long long)s3 * F + co));
        acc.x += w0 * v0.x; acc.y += w0 * v0.y;
        acc.x += w1 * v1.x; acc.y += w1 * v1.y;
        acc.x += w2 * v2.x; acc.y += w2 * v2.y;
        acc.x += w3 * v3.x; acc.y += w3 * v3.y;
    }
    for (; j < deg; j++) {
        unsigned long long a = __ldg(&sw[j]);
        int   s = (int)(unsigned int)a;
        float w = __uint_as_float((unsigned int)(a >> 32));
        float2 v = __ldg(reinterpret_cast<const float2*>(x + (long long)s * F + co));
        acc.x += w * v.x; acc.y += w * v.y;
    }

    *reinterpret_cast<float2*>(out + (long long)warp * F + co) = acc;  // single write; no memset of out
}

// ---------- 3. overflow fallback (normally count==0: immediate exit) ----------
__global__ void __launch_bounds__(THREADS)
k_fallback(const float* __restrict__ x, const float* __restrict__ ew,
           const int* __restrict__ ei, float* __restrict__ out, int E, int N)
{
    int n = g_cursor[N] * 16;
    for (int i = blockIdx.x * THREADS + threadIdx.x; i < n; i += gridDim.x * THREADS) {
        int e = g_ovf[i >> 4];
        int c = i & 15;
        int   s = __ldg(&ei[e]);
        int   d = __ldg(&ei[E + e]);
        float w = __ldg(&ew[e]);
        float4 v = __ldg(reinterpret_cast<const float4*>(x + (long long)s * F + c * 4));
        v.x *= w; v.y *= w; v.z *= w; v.w *= w;
        float* dp = out + (long long)d * F + c * 4;
        asm volatile("red.global.add.v4.f32 [%0], {%1, %2, %3, %4};"
                     :: "l"(dp), "f"(v.x), "f"(v.y), "f"(v.z), "f"(v.w) : "memory");
    }
}

extern "C" void kernel_launch(void* const* d_in, const int* in_sizes, int n_in,
                              void* d_out, int out_size)
{
    const float* x  = (const float*)d_in[0];
    const float* ew = (const float*)d_in[1];
    const int*   ei = (const int*)d_in[2];
    float* out = (float*)d_out;

    int E = in_sizes[2] / 2;
    int N = out_size / F;
    if (E > E_MAX || N > N_MAX) return;   // fixed problem: E=1M, N=100k

    void* cur_addr = nullptr;
    cudaGetSymbolAddress(&cur_addr, g_cursor);
    cudaMemsetAsync(cur_addr, 0, (size_t)(N + 1) * sizeof(int), 0);

    int bin_threads = (E >> 3) + (E & 7);
    k_binplace<<<(bin_threads + BIN_THREADS - 1) / BIN_THREADS, BIN_THREADS>>>(ew, ei, E, N);

    int blocks = (N * 32 + THREADS - 1) / THREADS;
    k_gather<<<blocks, THREADS>>>(x, out, N);

    k_fallback<<<8, THREADS>>>(x, ew, ei, out, E, N);
}